// round 11
// baseline (speedup 1.0000x reference)
#include <cuda_runtime.h>
#include <cuda_bf16.h>

// ---------------------------------------------------------------------------
// GATEncoder: 2-layer single-head GATConv (PyG semantics) on GB300 sm_103a.
// R9: R7's proven fp32 pipeline (fp16 gather reverted: aggregation is
// issue-bound, cvt doubled instr count) + R8's unordered-range CSR build
// (fused local scan + atomic base alloc; cursor pre-init so scatter's atomic
// is absolute). Self-restoring g_deg/g_alloc (reset by layer-2 aggregate).
// 7 kernel launches.
// ---------------------------------------------------------------------------

#define MAXN 50000
#define MAXE 800000
#define NEG_SLOPE 0.2f
#define EPS_DEN 1e-16f

__device__ __align__(16) float g_h[MAXN * 64];   // transformed features
__device__ __align__(16) float g_x1[MAXN * 64];  // layer-1 out / layer-2 in
__device__ float g_asrc[MAXN];
__device__ float g_adst[MAXN];
__device__ int   g_deg[MAXN];      // zero at entry; restored by agg2
__device__ int   g_cursor[MAXN];   // set by scan_alloc each run
__device__ int   g_indptr[MAXN];   // range start per node (unordered)
__device__ int   g_csr_src[MAXE];
__device__ int   g_alloc;          // zero at entry; restored by agg2

__device__ __forceinline__ float lrelu(float v) {
    return v > 0.f ? v : NEG_SLOPE * v;
}

__device__ __forceinline__ unsigned long long pack_dup(float v) {
    unsigned long long d;
    unsigned u = __float_as_uint(v);
    asm("mov.b64 %0, {%1, %1};" : "=l"(d) : "r"(u));
    return d;
}
__device__ __forceinline__ void ffma2(unsigned long long& acc,
                                      unsigned long long a,
                                      unsigned long long b) {
    asm("fma.rn.f32x2 %0, %1, %2, %0;" : "+l"(acc) : "l"(a), "l"(b));
}
__device__ __forceinline__ float2 unpack2(unsigned long long v) {
    unsigned lo, hi;
    asm("mov.b64 {%0, %1}, %2;" : "=r"(lo), "=r"(hi) : "l"(v));
    return make_float2(__uint_as_float(lo), __uint_as_float(hi));
}

// ---------------- CSR build ----------------
// 4 edges per thread via int4
__global__ void hist_kernel(const int* __restrict__ ei, int E, int n) {
    int t = blockIdx.x * blockDim.x + threadIdx.x;
    int j0 = t * 4;
    if (j0 + 3 < E) {
        int4 dv = *(const int4*)(ei + E + j0);
        if ((unsigned)dv.x < (unsigned)n) atomicAdd(&g_deg[dv.x], 1);
        if ((unsigned)dv.y < (unsigned)n) atomicAdd(&g_deg[dv.y], 1);
        if ((unsigned)dv.z < (unsigned)n) atomicAdd(&g_deg[dv.z], 1);
        if ((unsigned)dv.w < (unsigned)n) atomicAdd(&g_deg[dv.w], 1);
    } else {
        for (int j = j0; j < E; j++) {
            int d = ei[E + j];
            if ((unsigned)d < (unsigned)n) atomicAdd(&g_deg[d], 1);
        }
    }
}

// Local 1024-element exclusive scan per block; base offset from one atomic.
// Ranges across blocks are disjoint but unordered -- CSR doesn't care.
__global__ void scan_alloc_kernel(int n) {
    __shared__ int warp_sums[8];
    __shared__ int blk_base;
    int b = blockIdx.x, t = threadIdx.x;
    int base = b * 1024 + t * 4;
    int v[4];
    #pragma unroll
    for (int k = 0; k < 4; k++) {
        int idx = base + k;
        v[k] = (idx < n) ? g_deg[idx] : 0;
    }
    int s = v[0] + v[1] + v[2] + v[3];
    int lane = t & 31, wid = t >> 5;
    int incl = s;
    #pragma unroll
    for (int off = 1; off < 32; off <<= 1) {
        int x = __shfl_up_sync(0xffffffffu, incl, off);
        if (lane >= off) incl += x;
    }
    if (lane == 31) warp_sums[wid] = incl;
    __syncthreads();
    if (t == 0) {
        int tot = 0;
        #pragma unroll
        for (int k = 0; k < 8; k++) tot += warp_sums[k];
        blk_base = atomicAdd(&g_alloc, tot);
    }
    __syncthreads();
    int woff = 0;
    for (int k = 0; k < wid; k++) woff += warp_sums[k];
    int excl = blk_base + woff + incl - s;
    #pragma unroll
    for (int k = 0; k < 4; k++) {
        int idx = base + k;
        if (idx < n) { g_indptr[idx] = excl; g_cursor[idx] = excl; }
        excl += v[k];
    }
}

// cursor pre-initialized to range start: atomic returns absolute position
__global__ void scatter_kernel(const int* __restrict__ ei, int E, int n) {
    int t = blockIdx.x * blockDim.x + threadIdx.x;
    int j0 = t * 4;
    if (j0 + 3 < E) {
        int4 sv = *(const int4*)(ei + j0);
        int4 dv = *(const int4*)(ei + E + j0);
        int ss[4] = {sv.x, sv.y, sv.z, sv.w};
        int dd[4] = {dv.x, dv.y, dv.z, dv.w};
        #pragma unroll
        for (int k = 0; k < 4; k++) {
            int s = ss[k], d = dd[k];
            if (((unsigned)s < (unsigned)n) && ((unsigned)d < (unsigned)n)) {
                int pos = atomicAdd(&g_cursor[d], 1);
                g_csr_src[pos] = s;
            }
        }
    } else {
        for (int j = j0; j < E; j++) {
            int s = ei[j], d = ei[E + j];
            if (((unsigned)s < (unsigned)n) && ((unsigned)d < (unsigned)n)) {
                int pos = atomicAdd(&g_cursor[d], 1);
                g_csr_src[pos] = s;
            }
        }
    }
}

// ---------------- linear + attention scores ----------------
// h = in @ W (K -> 64) to g_h; a_src = h.att_s; a_dst = h.att_d.
// 256 threads, tile 128 rows x 64 cols, 8x4 outputs/thread; Xt transposed in
// smem (stride 130) so FFMA2 packs row-pairs; weight dups amortize over 8 rows.
template <int K, bool FROM_X1>
__global__ void __launch_bounds__(256) linear_att_kernel(
    const float* __restrict__ xin, const float* __restrict__ W,
    const float* __restrict__ att_s, const float* __restrict__ att_d, int n)
{
    constexpr int KC = 32;
    constexpr int ROWS = 128;
    __shared__ __align__(16) float Ws[KC][64];
    __shared__ __align__(16) float Xt[KC][130];   // [kk][row], even stride

    const float* x = FROM_X1 ? g_x1 : xin;
    int tid = threadIdx.x;
    int tx = tid & 15;          // cols 4*tx .. 4*tx+3
    int ty = tid >> 4;          // rows 8*ty .. 8*ty+7 (as 4 pairs)
    int row0 = blockIdx.x * ROWS;

    unsigned long long acc[4][4];   // [row-pair p][col c]
    #pragma unroll
    for (int p = 0; p < 4; p++)
        #pragma unroll
        for (int c = 0; c < 4; c++) acc[p][c] = 0ull;

    for (int kc = 0; kc < K; kc += KC) {
        __syncthreads();
        #pragma unroll
        for (int idx = tid; idx < KC * 64; idx += 256) {
            int kk = idx >> 6, c = idx & 63;
            Ws[kk][c] = W[(kc + kk) * 64 + c];
        }
        #pragma unroll
        for (int idx = tid; idx < ROWS * (KC / 4); idx += 256) {
            int row = idx >> 3, kq = idx & 7;
            int gr = row0 + row;
            float4 v = make_float4(0.f, 0.f, 0.f, 0.f);
            if (gr < n) v = *(const float4*)&x[(size_t)gr * K + kc + 4 * kq];
            Xt[4 * kq + 0][row] = v.x;
            Xt[4 * kq + 1][row] = v.y;
            Xt[4 * kq + 2][row] = v.z;
            Xt[4 * kq + 3][row] = v.w;
        }
        __syncthreads();

        #pragma unroll
        for (int kk = 0; kk < KC; kk++) {
            float4 wv = *(const float4*)&Ws[kk][4 * tx];
            unsigned long long wd0 = pack_dup(wv.x);
            unsigned long long wd1 = pack_dup(wv.y);
            unsigned long long wd2 = pack_dup(wv.z);
            unsigned long long wd3 = pack_dup(wv.w);
            unsigned long long xp[4];
            #pragma unroll
            for (int p = 0; p < 4; p++)
                xp[p] = *(const unsigned long long*)&Xt[kk][8 * ty + 2 * p];
            #pragma unroll
            for (int p = 0; p < 4; p++) {
                ffma2(acc[p][0], xp[p], wd0);
                ffma2(acc[p][1], xp[p], wd1);
                ffma2(acc[p][2], xp[p], wd2);
                ffma2(acc[p][3], xp[p], wd3);
            }
        }
    }

    // epilogue: 8 rows per thread; store h rows, fused attention scores
    float4 asv = *(const float4*)&att_s[4 * tx];
    float4 adv = *(const float4*)&att_d[4 * tx];
    #pragma unroll
    for (int p = 0; p < 4; p++) {
        float2 c0 = unpack2(acc[p][0]);
        float2 c1 = unpack2(acc[p][1]);
        float2 c2 = unpack2(acc[p][2]);
        float2 c3 = unpack2(acc[p][3]);
        #pragma unroll
        for (int half = 0; half < 2; half++) {
            int gr = row0 + 8 * ty + 2 * p + half;
            float4 hv = half ? make_float4(c0.y, c1.y, c2.y, c3.y)
                             : make_float4(c0.x, c1.x, c2.x, c3.x);
            if (gr < n) *(float4*)&g_h[(size_t)gr * 64 + 4 * tx] = hv;
            float vs = hv.x * asv.x + hv.y * asv.y + hv.z * asv.z + hv.w * asv.w;
            float vd = hv.x * adv.x + hv.y * adv.y + hv.z * adv.z + hv.w * adv.w;
            #pragma unroll
            for (int off = 8; off > 0; off >>= 1) {
                vs += __shfl_down_sync(0xffffffffu, vs, off, 16);
                vd += __shfl_down_sync(0xffffffffu, vd, off, 16);
            }
            if (tx == 0 && gr < n) { g_asrc[gr] = vs; g_adst[gr] = vd; }
        }
    }
}

// ---------------- aggregation: warp/node, 4 edges per iteration ----------
// 4 lane-groups of 8; group g handles edge (q*4+g), lane owns 8 features.
// out_i = (sum_j w_j h_j) / (sum_j w_j + eps) + bias, w_j = exp(lrelu(...)).
// TO_X1=false (layer 2) restores g_deg and g_alloc for the next replay.
template <bool TO_X1>
__global__ void __launch_bounds__(256) gat_aggregate_kernel(
    const float* __restrict__ bias, float* __restrict__ out, int n)
{
    int i = (blockIdx.x * blockDim.x + threadIdx.x) >> 5;
    int lane = threadIdx.x & 31;
    if (i >= n) return;
    int grp = lane >> 3, gl = lane & 7;

    int start = g_indptr[i];
    int deg   = g_deg[i];
    int end   = start + deg;
    if (!TO_X1 && lane == 0) {
        g_deg[i] = 0;                    // restore invariant for next run
        if (i == 0) g_alloc = 0;
    }
    float ad = g_adst[i];

    float w_self = __expf(lrelu(g_asrc[i] + ad));
    unsigned long long acc0 = 0ull, acc1 = 0ull, acc2 = 0ull, acc3 = 0ull;

    // self-loop: only group 0 accumulates (summed once in xor-reduction)
    if (grp == 0) {
        const float* hp = &g_h[(size_t)i * 64 + gl * 8];
        ulonglong2 v0 = *(const ulonglong2*)hp;
        ulonglong2 v1 = *(const ulonglong2*)(hp + 4);
        unsigned long long wd = pack_dup(w_self);
        ffma2(acc0, wd, v0.x); ffma2(acc1, wd, v0.y);
        ffma2(acc2, wd, v1.x); ffma2(acc3, wd, v1.y);
    }
    float den_l = (lane == 0) ? w_self : 0.f;

    for (int base = start; base < end; base += 32) {
        int jj = base + lane;
        int s_l = 0; float w_l = 0.f;
        if (jj < end) {
            s_l = g_csr_src[jj];
            w_l = __expf(lrelu(g_asrc[s_l] + ad));
        }
        den_l += w_l;
        int cnt = end - base; if (cnt > 32) cnt = 32;
        int nq = (cnt + 3) >> 2;
        for (int q = 0; q < nq; q++) {
            int src_lane = q * 4 + grp;
            int   s = __shfl_sync(0xffffffffu, s_l, src_lane);
            float w = __shfl_sync(0xffffffffu, w_l, src_lane);
            const float* hp = &g_h[(size_t)s * 64 + gl * 8];
            ulonglong2 v0 = *(const ulonglong2*)hp;
            ulonglong2 v1 = *(const ulonglong2*)(hp + 4);
            unsigned long long wd = pack_dup(w);
            ffma2(acc0, wd, v0.x); ffma2(acc1, wd, v0.y);
            ffma2(acc2, wd, v1.x); ffma2(acc3, wd, v1.y);
        }
    }

    // reduce den over whole warp
    #pragma unroll
    for (int off = 16; off > 0; off >>= 1)
        den_l += __shfl_xor_sync(0xffffffffu, den_l, off);
    float inv_den = 1.f / (den_l + EPS_DEN);

    // cross-group reduction (xor 8, 16) on 8 accumulated floats
    float2 f0 = unpack2(acc0), f1 = unpack2(acc1);
    float2 f2 = unpack2(acc2), f3 = unpack2(acc3);
    float f[8] = {f0.x, f0.y, f1.x, f1.y, f2.x, f2.y, f3.x, f3.y};
    #pragma unroll
    for (int k = 0; k < 8; k++) {
        f[k] += __shfl_xor_sync(0xffffffffu, f[k], 8);
        f[k] += __shfl_xor_sync(0xffffffffu, f[k], 16);
    }

    if (grp == 0) {
        const float4* bp = (const float4*)&bias[gl * 8];
        float4 b0 = bp[0], b1 = bp[1];
        float4 o0, o1;
        o0.x = f[0] * inv_den + b0.x;  o0.y = f[1] * inv_den + b0.y;
        o0.z = f[2] * inv_den + b0.z;  o0.w = f[3] * inv_den + b0.w;
        o1.x = f[4] * inv_den + b1.x;  o1.y = f[5] * inv_den + b1.y;
        o1.z = f[6] * inv_den + b1.z;  o1.w = f[7] * inv_den + b1.w;
        if (TO_X1) {
            o0.x = fmaxf(o0.x, 0.f); o0.y = fmaxf(o0.y, 0.f);
            o0.z = fmaxf(o0.z, 0.f); o0.w = fmaxf(o0.w, 0.f);
            o1.x = fmaxf(o1.x, 0.f); o1.y = fmaxf(o1.y, 0.f);
            o1.z = fmaxf(o1.z, 0.f); o1.w = fmaxf(o1.w, 0.f);
            float4* op = (float4*)&g_x1[(size_t)i * 64 + gl * 8];
            op[0] = o0; op[1] = o1;
        } else {
            float4* op = (float4*)&out[(size_t)i * 64 + gl * 8];
            op[0] = o0; op[1] = o1;
        }
    }
}

// ---------------------------------------------------------------------------
extern "C" void kernel_launch(void* const* d_in, const int* in_sizes, int n_in,
                              void* d_out, int out_size)
{
    const float* x   = (const float*)d_in[0];
    const int*   ei  = (const int*)d_in[1];     // int32 edge_index [2, E]
    const float* W1  = (const float*)d_in[2];
    const float* as1 = (const float*)d_in[3];
    const float* ad1 = (const float*)d_in[4];
    const float* b1  = (const float*)d_in[5];
    const float* W2  = (const float*)d_in[6];
    const float* as2 = (const float*)d_in[7];
    const float* ad2 = (const float*)d_in[8];
    const float* b2  = (const float*)d_in[9];
    float* out = (float*)d_out;
    (void)n_in; (void)out_size;

    int n = in_sizes[0] / 128;
    int E = in_sizes[1] / 2;
    if (n > MAXN) n = MAXN;
    if (E > MAXE) E = MAXE;

    int scan_blocks = (n + 1023) / 1024;
    int e4_threads  = (E + 3) / 4;

    // ---- CSR build: hist -> fused scan+alloc -> scatter (3 launches) ----
    hist_kernel<<<(e4_threads + 255) / 256, 256>>>(ei, E, n);
    scan_alloc_kernel<<<scan_blocks, 256>>>(n);
    scatter_kernel<<<(e4_threads + 255) / 256, 256>>>(ei, E, n);

    int lin_blocks = (n + 127) / 128;
    int agg_blocks = (n + 7) / 8;   // warp per node, 8 warps/block

    // ---- Layer 1: h = x@W1; x1 = relu(aggregate(h) + b1) ----
    linear_att_kernel<128, false><<<lin_blocks, 256>>>(x, W1, as1, ad1, n);
    gat_aggregate_kernel<true><<<agg_blocks, 256>>>(b1, nullptr, n);

    // ---- Layer 2: h = x1@W2; out = aggregate(h) + b2 ----
    linear_att_kernel<64, true><<<lin_blocks, 256>>>(nullptr, W2, as2, ad2, n);
    gat_aggregate_kernel<false><<<agg_blocks, 256>>>(b2, out, n);
}

// round 15
// speedup vs baseline: 1.2936x; 1.2936x over previous
#include <cuda_runtime.h>
#include <cuda_bf16.h>

// ---------------------------------------------------------------------------
// GATEncoder: 2-layer single-head GATConv (PyG semantics) on GB300 sm_103a.
// R10: exact R7 pipeline restored (the R8/R9 "unordered-range CSR" scheme
// regressed ~35us in two independent rounds -> reverted). One fix on top:
// indptr_kernel's serial per-block partial-sum loop (t0, up to 49 L2 loads
// back-to-back) replaced by a warp-parallel masked reduction.
// ---------------------------------------------------------------------------

#define MAXN 50000
#define MAXE 800000
#define NEG_SLOPE 0.2f
#define EPS_DEN 1e-16f

__device__ __align__(16) float g_h[MAXN * 64];   // transformed features
__device__ __align__(16) float g_x1[MAXN * 64];  // layer-1 out / layer-2 in
__device__ float g_asrc[MAXN];
__device__ float g_adst[MAXN];
__device__ int   g_deg[MAXN];
__device__ int   g_cursor[MAXN];
__device__ int   g_indptr[MAXN + 1];
__device__ int   g_csr_src[MAXE];
__device__ int   g_part[64];        // only first scan_blocks entries written

__device__ __forceinline__ float lrelu(float v) {
    return v > 0.f ? v : NEG_SLOPE * v;
}

__device__ __forceinline__ unsigned long long pack_dup(float v) {
    unsigned long long d;
    unsigned u = __float_as_uint(v);
    asm("mov.b64 %0, {%1, %1};" : "=l"(d) : "r"(u));
    return d;
}
__device__ __forceinline__ void ffma2(unsigned long long& acc,
                                      unsigned long long a,
                                      unsigned long long b) {
    asm("fma.rn.f32x2 %0, %1, %2, %0;" : "+l"(acc) : "l"(a), "l"(b));
}
__device__ __forceinline__ float2 unpack2(unsigned long long v) {
    unsigned lo, hi;
    asm("mov.b64 {%0, %1}, %2;" : "=r"(lo), "=r"(hi) : "l"(v));
    return make_float2(__uint_as_float(lo), __uint_as_float(hi));
}

// ---------------- CSR build ----------------
__global__ void zero_counts_kernel(int n) {
    int i = blockIdx.x * blockDim.x + threadIdx.x;
    if (i < n) { g_deg[i] = 0; g_cursor[i] = 0; }
}

// 4 edges per thread via int4
__global__ void hist_kernel(const int* __restrict__ ei, int E, int n) {
    int t = blockIdx.x * blockDim.x + threadIdx.x;
    int j0 = t * 4;
    if (j0 + 3 < E) {
        int4 dv = *(const int4*)(ei + E + j0);
        if ((unsigned)dv.x < (unsigned)n) atomicAdd(&g_deg[dv.x], 1);
        if ((unsigned)dv.y < (unsigned)n) atomicAdd(&g_deg[dv.y], 1);
        if ((unsigned)dv.z < (unsigned)n) atomicAdd(&g_deg[dv.z], 1);
        if ((unsigned)dv.w < (unsigned)n) atomicAdd(&g_deg[dv.w], 1);
    } else {
        for (int j = j0; j < E; j++) {
            int d = ei[E + j];
            if ((unsigned)d < (unsigned)n) atomicAdd(&g_deg[d], 1);
        }
    }
}

// 1024 elements per block, 4 per thread: per-block sums of g_deg
__global__ void block_sum_kernel(int n) {
    __shared__ int sm[256];
    int b = blockIdx.x, t = threadIdx.x;
    int base = b * 1024 + t * 4;
    int s = 0;
    #pragma unroll
    for (int k = 0; k < 4; k++) {
        int idx = base + k;
        if (idx < n) s += g_deg[idx];
    }
    sm[t] = s;
    __syncthreads();
    for (int off = 128; off > 0; off >>= 1) {
        if (t < off) sm[t] += sm[t + off];
        __syncthreads();
    }
    if (t == 0) g_part[b] = sm[0];
}

// exclusive scan -> g_indptr; block offset via warp-parallel masked reduction
// (g_part entries >= gridDim.x are never written and remain 0 from zero-init)
__global__ void indptr_kernel(int n) {
    __shared__ int warp_sums[8];
    __shared__ int blk_off_s;
    int b = blockIdx.x, t = threadIdx.x;
    if (t < 32) {
        int p0 = (t < b)      ? g_part[t]      : 0;
        int p1 = (t + 32 < b) ? g_part[t + 32] : 0;
        int o = p0 + p1;
        #pragma unroll
        for (int off = 16; off > 0; off >>= 1)
            o += __shfl_xor_sync(0xffffffffu, o, off);
        if (t == 0) blk_off_s = o;
    }
    int base = b * 1024 + t * 4;
    int v[4];
    #pragma unroll
    for (int k = 0; k < 4; k++) {
        int idx = base + k;
        v[k] = (idx < n) ? g_deg[idx] : 0;
    }
    int s = v[0] + v[1] + v[2] + v[3];
    int lane = t & 31, wid = t >> 5;
    int incl = s;
    #pragma unroll
    for (int off = 1; off < 32; off <<= 1) {
        int x = __shfl_up_sync(0xffffffffu, incl, off);
        if (lane >= off) incl += x;
    }
    if (lane == 31) warp_sums[wid] = incl;
    __syncthreads();
    int woff = 0;
    for (int k = 0; k < wid; k++) woff += warp_sums[k];
    int excl = blk_off_s + woff + incl - s;
    #pragma unroll
    for (int k = 0; k < 4; k++) {
        int idx = base + k;
        if (idx < n)       g_indptr[idx] = excl;
        else if (idx == n) g_indptr[n]   = excl;
        excl += v[k];
    }
}

__global__ void scatter_kernel(const int* __restrict__ ei, int E, int n) {
    int t = blockIdx.x * blockDim.x + threadIdx.x;
    int j0 = t * 4;
    if (j0 + 3 < E) {
        int4 sv = *(const int4*)(ei + j0);
        int4 dv = *(const int4*)(ei + E + j0);
        int ss[4] = {sv.x, sv.y, sv.z, sv.w};
        int dd[4] = {dv.x, dv.y, dv.z, dv.w};
        #pragma unroll
        for (int k = 0; k < 4; k++) {
            int s = ss[k], d = dd[k];
            if (((unsigned)s < (unsigned)n) && ((unsigned)d < (unsigned)n)) {
                int pos = atomicAdd(&g_cursor[d], 1);
                g_csr_src[g_indptr[d] + pos] = s;
            }
        }
    } else {
        for (int j = j0; j < E; j++) {
            int s = ei[j], d = ei[E + j];
            if (((unsigned)s < (unsigned)n) && ((unsigned)d < (unsigned)n)) {
                int pos = atomicAdd(&g_cursor[d], 1);
                g_csr_src[g_indptr[d] + pos] = s;
            }
        }
    }
}

// ---------------- linear + attention scores ----------------
// h = in @ W (K -> 64) to g_h; a_src = h.att_s; a_dst = h.att_d.
// 256 threads, tile 128 rows x 64 cols, 8x4 outputs/thread; Xt transposed in
// smem (stride 130) so FFMA2 packs row-pairs; weight dups amortize over 8 rows.
template <int K, bool FROM_X1>
__global__ void __launch_bounds__(256) linear_att_kernel(
    const float* __restrict__ xin, const float* __restrict__ W,
    const float* __restrict__ att_s, const float* __restrict__ att_d, int n)
{
    constexpr int KC = 32;
    constexpr int ROWS = 128;
    __shared__ __align__(16) float Ws[KC][64];
    __shared__ __align__(16) float Xt[KC][130];   // [kk][row], even stride

    const float* x = FROM_X1 ? g_x1 : xin;
    int tid = threadIdx.x;
    int tx = tid & 15;          // cols 4*tx .. 4*tx+3
    int ty = tid >> 4;          // rows 8*ty .. 8*ty+7 (as 4 pairs)
    int row0 = blockIdx.x * ROWS;

    unsigned long long acc[4][4];   // [row-pair p][col c]
    #pragma unroll
    for (int p = 0; p < 4; p++)
        #pragma unroll
        for (int c = 0; c < 4; c++) acc[p][c] = 0ull;

    for (int kc = 0; kc < K; kc += KC) {
        __syncthreads();
        #pragma unroll
        for (int idx = tid; idx < KC * 64; idx += 256) {
            int kk = idx >> 6, c = idx & 63;
            Ws[kk][c] = W[(kc + kk) * 64 + c];
        }
        #pragma unroll
        for (int idx = tid; idx < ROWS * (KC / 4); idx += 256) {
            int row = idx >> 3, kq = idx & 7;
            int gr = row0 + row;
            float4 v = make_float4(0.f, 0.f, 0.f, 0.f);
            if (gr < n) v = *(const float4*)&x[(size_t)gr * K + kc + 4 * kq];
            Xt[4 * kq + 0][row] = v.x;
            Xt[4 * kq + 1][row] = v.y;
            Xt[4 * kq + 2][row] = v.z;
            Xt[4 * kq + 3][row] = v.w;
        }
        __syncthreads();

        #pragma unroll
        for (int kk = 0; kk < KC; kk++) {
            float4 wv = *(const float4*)&Ws[kk][4 * tx];
            unsigned long long wd0 = pack_dup(wv.x);
            unsigned long long wd1 = pack_dup(wv.y);
            unsigned long long wd2 = pack_dup(wv.z);
            unsigned long long wd3 = pack_dup(wv.w);
            unsigned long long xp[4];
            #pragma unroll
            for (int p = 0; p < 4; p++)
                xp[p] = *(const unsigned long long*)&Xt[kk][8 * ty + 2 * p];
            #pragma unroll
            for (int p = 0; p < 4; p++) {
                ffma2(acc[p][0], xp[p], wd0);
                ffma2(acc[p][1], xp[p], wd1);
                ffma2(acc[p][2], xp[p], wd2);
                ffma2(acc[p][3], xp[p], wd3);
            }
        }
    }

    // epilogue: 8 rows per thread; store h rows, fused attention scores
    float4 asv = *(const float4*)&att_s[4 * tx];
    float4 adv = *(const float4*)&att_d[4 * tx];
    #pragma unroll
    for (int p = 0; p < 4; p++) {
        float2 c0 = unpack2(acc[p][0]);
        float2 c1 = unpack2(acc[p][1]);
        float2 c2 = unpack2(acc[p][2]);
        float2 c3 = unpack2(acc[p][3]);
        #pragma unroll
        for (int half = 0; half < 2; half++) {
            int gr = row0 + 8 * ty + 2 * p + half;
            float4 hv = half ? make_float4(c0.y, c1.y, c2.y, c3.y)
                             : make_float4(c0.x, c1.x, c2.x, c3.x);
            if (gr < n) *(float4*)&g_h[(size_t)gr * 64 + 4 * tx] = hv;
            float vs = hv.x * asv.x + hv.y * asv.y + hv.z * asv.z + hv.w * asv.w;
            float vd = hv.x * adv.x + hv.y * adv.y + hv.z * adv.z + hv.w * adv.w;
            #pragma unroll
            for (int off = 8; off > 0; off >>= 1) {
                vs += __shfl_down_sync(0xffffffffu, vs, off, 16);
                vd += __shfl_down_sync(0xffffffffu, vd, off, 16);
            }
            if (tx == 0 && gr < n) { g_asrc[gr] = vs; g_adst[gr] = vd; }
        }
    }
}

// ---------------- aggregation: warp/node, 4 edges per iteration ----------
// 4 lane-groups of 8; group g handles edge (q*4+g), lane owns 8 features.
// out_i = (sum_j w_j h_j) / (sum_j w_j + eps) + bias, w_j = exp(lrelu(...)).
template <bool TO_X1>
__global__ void __launch_bounds__(256) gat_aggregate_kernel(
    const float* __restrict__ bias, float* __restrict__ out, int n)
{
    int i = (blockIdx.x * blockDim.x + threadIdx.x) >> 5;
    int lane = threadIdx.x & 31;
    if (i >= n) return;
    int grp = lane >> 3, gl = lane & 7;

    int start = g_indptr[i];
    int end   = g_indptr[i + 1];
    float ad = g_adst[i];

    float w_self = __expf(lrelu(g_asrc[i] + ad));
    unsigned long long acc0 = 0ull, acc1 = 0ull, acc2 = 0ull, acc3 = 0ull;

    // self-loop: only group 0 accumulates (summed once in xor-reduction)
    if (grp == 0) {
        const float* hp = &g_h[(size_t)i * 64 + gl * 8];
        ulonglong2 v0 = *(const ulonglong2*)hp;
        ulonglong2 v1 = *(const ulonglong2*)(hp + 4);
        unsigned long long wd = pack_dup(w_self);
        ffma2(acc0, wd, v0.x); ffma2(acc1, wd, v0.y);
        ffma2(acc2, wd, v1.x); ffma2(acc3, wd, v1.y);
    }
    float den_l = (lane == 0) ? w_self : 0.f;

    for (int base = start; base < end; base += 32) {
        int jj = base + lane;
        int s_l = 0; float w_l = 0.f;
        if (jj < end) {
            s_l = g_csr_src[jj];
            w_l = __expf(lrelu(g_asrc[s_l] + ad));
        }
        den_l += w_l;
        int cnt = end - base; if (cnt > 32) cnt = 32;
        int nq = (cnt + 3) >> 2;
        for (int q = 0; q < nq; q++) {
            int src_lane = q * 4 + grp;
            int   s = __shfl_sync(0xffffffffu, s_l, src_lane);
            float w = __shfl_sync(0xffffffffu, w_l, src_lane);
            const float* hp = &g_h[(size_t)s * 64 + gl * 8];
            ulonglong2 v0 = *(const ulonglong2*)hp;
            ulonglong2 v1 = *(const ulonglong2*)(hp + 4);
            unsigned long long wd = pack_dup(w);
            ffma2(acc0, wd, v0.x); ffma2(acc1, wd, v0.y);
            ffma2(acc2, wd, v1.x); ffma2(acc3, wd, v1.y);
        }
    }

    // reduce den over whole warp
    #pragma unroll
    for (int off = 16; off > 0; off >>= 1)
        den_l += __shfl_xor_sync(0xffffffffu, den_l, off);
    float inv_den = 1.f / (den_l + EPS_DEN);

    // cross-group reduction (xor 8, 16) on 8 accumulated floats
    float2 f0 = unpack2(acc0), f1 = unpack2(acc1);
    float2 f2 = unpack2(acc2), f3 = unpack2(acc3);
    float f[8] = {f0.x, f0.y, f1.x, f1.y, f2.x, f2.y, f3.x, f3.y};
    #pragma unroll
    for (int k = 0; k < 8; k++) {
        f[k] += __shfl_xor_sync(0xffffffffu, f[k], 8);
        f[k] += __shfl_xor_sync(0xffffffffu, f[k], 16);
    }

    if (grp == 0) {
        const float4* bp = (const float4*)&bias[gl * 8];
        float4 b0 = bp[0], b1 = bp[1];
        float4 o0, o1;
        o0.x = f[0] * inv_den + b0.x;  o0.y = f[1] * inv_den + b0.y;
        o0.z = f[2] * inv_den + b0.z;  o0.w = f[3] * inv_den + b0.w;
        o1.x = f[4] * inv_den + b1.x;  o1.y = f[5] * inv_den + b1.y;
        o1.z = f[6] * inv_den + b1.z;  o1.w = f[7] * inv_den + b1.w;
        if (TO_X1) {
            o0.x = fmaxf(o0.x, 0.f); o0.y = fmaxf(o0.y, 0.f);
            o0.z = fmaxf(o0.z, 0.f); o0.w = fmaxf(o0.w, 0.f);
            o1.x = fmaxf(o1.x, 0.f); o1.y = fmaxf(o1.y, 0.f);
            o1.z = fmaxf(o1.z, 0.f); o1.w = fmaxf(o1.w, 0.f);
            float4* op = (float4*)&g_x1[(size_t)i * 64 + gl * 8];
            op[0] = o0; op[1] = o1;
        } else {
            float4* op = (float4*)&out[(size_t)i * 64 + gl * 8];
            op[0] = o0; op[1] = o1;
        }
    }
}

// ---------------------------------------------------------------------------
extern "C" void kernel_launch(void* const* d_in, const int* in_sizes, int n_in,
                              void* d_out, int out_size)
{
    const float* x   = (const float*)d_in[0];
    const int*   ei  = (const int*)d_in[1];     // int32 edge_index [2, E]
    const float* W1  = (const float*)d_in[2];
    const float* as1 = (const float*)d_in[3];
    const float* ad1 = (const float*)d_in[4];
    const float* b1  = (const float*)d_in[5];
    const float* W2  = (const float*)d_in[6];
    const float* as2 = (const float*)d_in[7];
    const float* ad2 = (const float*)d_in[8];
    const float* b2  = (const float*)d_in[9];
    float* out = (float*)d_out;
    (void)n_in; (void)out_size;

    int n = in_sizes[0] / 128;
    int E = in_sizes[1] / 2;
    if (n > MAXN) n = MAXN;
    if (E > MAXE) E = MAXE;

    int scan_blocks = (n + 1023) / 1024;
    int e4_threads  = (E + 3) / 4;

    // ---- CSR build (shared by both layers) ----
    zero_counts_kernel<<<(n + 255) / 256, 256>>>(n);
    hist_kernel<<<(e4_threads + 255) / 256, 256>>>(ei, E, n);
    block_sum_kernel<<<scan_blocks, 256>>>(n);
    indptr_kernel<<<scan_blocks, 256>>>(n);
    scatter_kernel<<<(e4_threads + 255) / 256, 256>>>(ei, E, n);

    int lin_blocks = (n + 127) / 128;
    int agg_blocks = (n + 7) / 8;   // warp per node, 8 warps/block

    // ---- Layer 1: h = x@W1; x1 = relu(aggregate(h) + b1) ----
    linear_att_kernel<128, false><<<lin_blocks, 256>>>(x, W1, as1, ad1, n);
    gat_aggregate_kernel<true><<<agg_blocks, 256>>>(b1, nullptr, n);

    // ---- Layer 2: h = x1@W2; out = aggregate(h) + b2 ----
    linear_att_kernel<64, true><<<lin_blocks, 256>>>(nullptr, W2, as2, ad2, n);
    gat_aggregate_kernel<false><<<agg_blocks, 256>>>(b2, out, n);
}